// round 3
// baseline (speedup 1.0000x reference)
#include <cuda_runtime.h>
#include <cstdint>

#define N_HEADS   16
#define HEAD_DIM  128
#define FF_DIM    512
#define D_MODEL   2048
#define TILE_M    128
#define FFC       64
#define NCH       (FF_DIM / FFC)   // 8
#define THREADS   256

// tf32-pre-rounded weights (same layout as inputs, no transpose needed)
__device__ float g_W1r[N_HEADS * HEAD_DIM * FF_DIM];   // [h][d][f]
__device__ float g_W2r[N_HEADS * FF_DIM * HEAD_DIM];   // [h][f][d]

// SMEM strides in floats (A tiles: stride%32==4 ; B tiles: stride%32==8)
#define LDX   132
#define LDH   68
#define LDW1  72
#define LDW2  136

// SMEM byte offsets
static constexpr int SM_X  = 0;                         // 128*132*4 = 67584
static constexpr int SM_H  = 67584;                     // 128*68*4  = 34816
static constexpr int SM_WA = 102400;                    // 128*72*4  = 36864  (W1 chunk)
static constexpr int SM_WB = 139264;                    // 64*136*4  = 34816  (W2 chunk)
static constexpr int SM_B1 = 174080;                    // 512 floats
static constexpr int SM_B2 = 176128;                    // 128 floats
static constexpr int SMEM_TOTAL = 176640;

// ---------------------------------------------------------------- helpers ---
__device__ __forceinline__ uint32_t f2tf32(float f) {
    uint32_t r;
    asm("cvt.rna.tf32.f32 %0, %1;" : "=r"(r) : "f"(f));
    return r;
}
__device__ __forceinline__ uint32_t smem_u32(const void* p) {
    uint32_t a;
    asm("{ .reg .u64 t; cvta.to.shared.u64 t, %1; cvt.u32.u64 %0, t; }" : "=r"(a) : "l"(p));
    return a;
}
__device__ __forceinline__ void cp16(uint32_t s, const void* g) {
    asm volatile("cp.async.ca.shared.global [%0], [%1], 16;" :: "r"(s), "l"(g));
}
#define CP_COMMIT() asm volatile("cp.async.commit_group;" ::: "memory")
#define CP_WAIT1()  asm volatile("cp.async.wait_group 1;" ::: "memory")

__device__ __forceinline__ void mma_tf32(float* d, const uint32_t* a, const uint32_t* b) {
    asm volatile(
        "mma.sync.aligned.m16n8k8.row.col.f32.tf32.tf32.f32 "
        "{%0,%1,%2,%3}, {%4,%5,%6,%7}, {%8,%9}, {%0,%1,%2,%3};"
        : "+f"(d[0]), "+f"(d[1]), "+f"(d[2]), "+f"(d[3])
        : "r"(a[0]), "r"(a[1]), "r"(a[2]), "r"(a[3]), "r"(b[0]), "r"(b[1]));
}

// ------------------------------------------------ weight tf32 pre-round -----
__global__ void round_kernel(const float* __restrict__ w1, const float* __restrict__ w2) {
    int i = blockIdx.x * blockDim.x + threadIdx.x;   // 0 .. 2^20-1 (grid sized exactly)
    g_W1r[i] = __uint_as_float(f2tf32(w1[i]));
    g_W2r[i] = __uint_as_float(f2tf32(w2[i]));
}

// ----------------------------------------------------------- main kernel ----
__global__ void __launch_bounds__(THREADS, 1)
ffn_kernel(const float* __restrict__ x, const float* __restrict__ b1,
           const float* __restrict__ b2, float* __restrict__ out) {
    extern __shared__ char smem[];
    const int tid  = threadIdx.x;
    const int lane = tid & 31;
    const int warp = tid >> 5;
    const int g    = lane >> 2;        // groupID 0..7
    const int t    = lane & 3;         // thread-in-group 0..3
    const int wr   = warp >> 1;        // 0..3  (row group)
    const int wc   = warp & 1;         // 0..1  (col group)
    const int r0   = wr * 32;

    const int head = blockIdx.y;
    const int t0   = blockIdx.x * TILE_M;
    const uint32_t sb = smem_u32(smem);

    float* Xs  = reinterpret_cast<float*>(smem + SM_X);
    float* Hs  = reinterpret_cast<float*>(smem + SM_H);
    float* W1s = reinterpret_cast<float*>(smem + SM_WA);
    float* W2s = reinterpret_cast<float*>(smem + SM_WB);
    float* b1s = reinterpret_cast<float*>(smem + SM_B1);
    float* b2s = reinterpret_cast<float*>(smem + SM_B2);

    const float* W1h = g_W1r + (size_t)head * HEAD_DIM * FF_DIM;   // [128][512]
    const float* W2h = g_W2r + (size_t)head * FF_DIM * HEAD_DIM;   // [512][128]

    // --- issue W1_0 (group 0) and W2_0 (group 1) via cp.async -------------
    {
        // W1 chunk 0: 128 rows x 64 cols (16 float4/row) = 2048 segs / 256 thr
        #pragma unroll
        for (int i = 0; i < 8; ++i) {
            int idx = tid + i * THREADS;
            int row = idx >> 4, c4 = (idx & 15) << 2;
            cp16(sb + SM_WA + (uint32_t)(row * LDW1 + c4) * 4, W1h + row * FF_DIM + c4);
        }
        CP_COMMIT();
        // W2 chunk 0: 64 rows x 128 cols (32 float4/row) = 2048 segs
        #pragma unroll
        for (int i = 0; i < 8; ++i) {
            int idx = tid + i * THREADS;
            int row = idx >> 5, c4 = (idx & 31) << 2;
            cp16(sb + SM_WB + (uint32_t)(row * LDW2 + c4) * 4, W2h + row * HEAD_DIM + c4);
        }
        CP_COMMIT();
    }

    // --- biases + x tile (tf32 pre-round) ---------------------------------
    for (int i = tid; i < FF_DIM; i += THREADS)  b1s[i] = b1[head * FF_DIM + i];
    if (tid < HEAD_DIM) b2s[tid] = b2[head * HEAD_DIM + tid];

    #pragma unroll
    for (int i = 0; i < 16; ++i) {
        int u = tid + i * THREADS;            // 4096 float4 segments
        int row = u >> 5, c4 = (u & 31) << 2;
        float4 v = *reinterpret_cast<const float4*>(
            x + (size_t)(t0 + row) * D_MODEL + head * HEAD_DIM + c4);
        Xs[row * LDX + c4 + 0] = __uint_as_float(f2tf32(v.x));
        Xs[row * LDX + c4 + 1] = __uint_as_float(f2tf32(v.y));
        Xs[row * LDX + c4 + 2] = __uint_as_float(f2tf32(v.z));
        Xs[row * LDX + c4 + 3] = __uint_as_float(f2tf32(v.w));
    }
    __syncthreads();

    float acc2[2][8][4];
    #pragma unroll
    for (int mi = 0; mi < 2; ++mi)
        #pragma unroll
        for (int ni = 0; ni < 8; ++ni)
            #pragma unroll
            for (int e = 0; e < 4; ++e) acc2[mi][ni][e] = 0.0f;

    for (int c = 0; c < NCH; ++c) {
        // ---- wait W1_c, sync (also fences MMA2_{c-1} H reads) ------------
        CP_WAIT1();
        __syncthreads();

        // ---- MMA1: h_chunk[128x64] = X[128x128] @ W1c[128x64] ------------
        float acc1[2][4][4];
        #pragma unroll
        for (int mi = 0; mi < 2; ++mi)
            #pragma unroll
            for (int ni = 0; ni < 4; ++ni)
                #pragma unroll
                for (int e = 0; e < 4; ++e) acc1[mi][ni][e] = 0.0f;

        #pragma unroll
        for (int ks = 0; ks < 16; ++ks) {
            const int k0 = ks * 8;
            uint32_t a[2][4];
            #pragma unroll
            for (int mi = 0; mi < 2; ++mi) {
                const int rb = r0 + mi * 16;
                a[mi][0] = __float_as_uint(Xs[(rb + g) * LDX + k0 + t]);
                a[mi][1] = __float_as_uint(Xs[(rb + 8 + g) * LDX + k0 + t]);
                a[mi][2] = __float_as_uint(Xs[(rb + g) * LDX + k0 + 4 + t]);
                a[mi][3] = __float_as_uint(Xs[(rb + 8 + g) * LDX + k0 + 4 + t]);
            }
            uint32_t bf[4][2];
            #pragma unroll
            for (int ni = 0; ni < 4; ++ni) {
                const int col = wc * 32 + ni * 8 + g;
                bf[ni][0] = __float_as_uint(W1s[(k0 + t) * LDW1 + col]);
                bf[ni][1] = __float_as_uint(W1s[(k0 + 4 + t) * LDW1 + col]);
            }
            #pragma unroll
            for (int mi = 0; mi < 2; ++mi)
                #pragma unroll
                for (int ni = 0; ni < 4; ++ni)
                    mma_tf32(acc1[mi][ni], a[mi], bf[ni]);
        }
        __syncthreads();   // all warps done reading WA

        // ---- prefetch W1_{c+1} into WA (group 2c+2; empty group if last) --
        if (c + 1 < NCH) {
            const float* src = W1h + (size_t)(c + 1) * FFC;
            #pragma unroll
            for (int i = 0; i < 8; ++i) {
                int idx = tid + i * THREADS;
                int row = idx >> 4, c4 = (idx & 15) << 2;
                cp16(sb + SM_WA + (uint32_t)(row * LDW1 + c4) * 4, src + row * FF_DIM + c4);
            }
        }
        CP_COMMIT();

        // ---- bias + relu + tf32-round -> H -------------------------------
        #pragma unroll
        for (int mi = 0; mi < 2; ++mi)
            #pragma unroll
            for (int ni = 0; ni < 4; ++ni)
                #pragma unroll
                for (int e = 0; e < 4; ++e) {
                    const int row = r0 + mi * 16 + g + ((e >= 2) ? 8 : 0);
                    const int col = wc * 32 + ni * 8 + 2 * t + (e & 1);
                    float v = acc1[mi][ni][e] + b1s[c * FFC + col];
                    Hs[row * LDH + col] = __uint_as_float(f2tf32(fmaxf(v, 0.0f)));
                }

        // ---- wait W2_c, sync (publishes H too) ---------------------------
        CP_WAIT1();
        __syncthreads();

        // ---- MMA2: out[128x128] += H[128x64] @ W2c[64x128] ---------------
        #pragma unroll
        for (int ks = 0; ks < 8; ++ks) {
            const int k0 = ks * 8;
            uint32_t a[2][4];
            #pragma unroll
            for (int mi = 0; mi < 2; ++mi) {
                const int rb = r0 + mi * 16;
                a[mi][0] = __float_as_uint(Hs[(rb + g) * LDH + k0 + t]);
                a[mi][1] = __float_as_uint(Hs[(rb + 8 + g) * LDH + k0 + t]);
                a[mi][2] = __float_as_uint(Hs[(rb + g) * LDH + k0 + 4 + t]);
                a[mi][3] = __float_as_uint(Hs[(rb + 8 + g) * LDH + k0 + 4 + t]);
            }
            uint32_t bf[8][2];
            #pragma unroll
            for (int ni = 0; ni < 8; ++ni) {
                const int col = wc * 64 + ni * 8 + g;
                bf[ni][0] = __float_as_uint(W2s[(k0 + t) * LDW2 + col]);
                bf[ni][1] = __float_as_uint(W2s[(k0 + 4 + t) * LDW2 + col]);
            }
            #pragma unroll
            for (int mi = 0; mi < 2; ++mi)
                #pragma unroll
                for (int ni = 0; ni < 8; ++ni)
                    mma_tf32(acc2[mi][ni], a[mi], bf[ni]);
        }
        __syncthreads();   // all warps done reading WB

        // ---- prefetch W2_{c+1} into WB (group 2c+3; empty if last) -------
        if (c + 1 < NCH) {
            const float* src = W2h + (size_t)(c + 1) * FFC * HEAD_DIM;
            #pragma unroll
            for (int i = 0; i < 8; ++i) {
                int idx = tid + i * THREADS;
                int row = idx >> 5, c4 = (idx & 31) << 2;
                cp16(sb + SM_WB + (uint32_t)(row * LDW2 + c4) * 4, src + row * HEAD_DIM + c4);
            }
        }
        CP_COMMIT();
    }

    // ---- epilogue: out += b2, stage through Xs for coalesced stores ------
    #pragma unroll
    for (int mi = 0; mi < 2; ++mi)
        #pragma unroll
        for (int ni = 0; ni < 8; ++ni)
            #pragma unroll
            for (int e = 0; e < 4; ++e) {
                const int row = r0 + mi * 16 + g + ((e >= 2) ? 8 : 0);
                const int col = wc * 64 + ni * 8 + 2 * t + (e & 1);
                Xs[row * LDX + col] = acc2[mi][ni][e] + b2s[col];
            }
    __syncthreads();
    #pragma unroll
    for (int i = 0; i < 16; ++i) {
        int u = tid + i * THREADS;
        int row = u >> 5, c4 = (u & 31) << 2;
        float4 v;
        v.x = Xs[row * LDX + c4 + 0];
        v.y = Xs[row * LDX + c4 + 1];
        v.z = Xs[row * LDX + c4 + 2];
        v.w = Xs[row * LDX + c4 + 3];
        *reinterpret_cast<float4*>(
            out + (size_t)(t0 + row) * D_MODEL + head * HEAD_DIM + c4) = v;
    }
}

// -------------------------------------------------------------- launch ------
extern "C" void kernel_launch(void* const* d_in, const int* in_sizes, int n_in,
                              void* d_out, int out_size) {
    const float* x  = (const float*)d_in[0];
    const float* W1 = (const float*)d_in[1];
    const float* b1 = (const float*)d_in[2];
    const float* W2 = (const float*)d_in[3];
    const float* b2 = (const float*)d_in[4];
    float* out = (float*)d_out;

    // 16*128*512 = 2^20 elements each — grid covers exactly
    round_kernel<<<4096, 256>>>(W1, W2);

    cudaFuncSetAttribute(ffn_kernel, cudaFuncAttributeMaxDynamicSharedMemorySize, SMEM_TOTAL);
    ffn_kernel<<<dim3(16384 / TILE_M, N_HEADS), THREADS, SMEM_TOTAL>>>(x, b1, b2, out);
}

// round 4
// speedup vs baseline: 1.6568x; 1.6568x over previous
#include <cuda_runtime.h>
#include <cuda_fp16.h>
#include <cstdint>

#define N_HEADS   16
#define HEAD_DIM  128
#define FF_DIM    512
#define D_MODEL   2048
#define TILE_M    128
#define FFC       64
#define NCH       (FF_DIM / FFC)   // 8
#define THREADS   256

// fp16 weights in B-fragment-major order (built once per launch)
__device__ __half g_W1f[N_HEADS * HEAD_DIM * FF_DIM];   // 2 MB
__device__ __half g_W2f[N_HEADS * FF_DIM * HEAD_DIM];   // 2 MB

// --------------------------------------------------------- SMEM layout ------
// Xfrag: [rb:8][ks:8][chunk:32][16B]  (A-frag fp16, swizzled chunk = (g*4+t)^ks)
// Hfrag: [rb:8][ks:4][chunk:32][16B]
// WA   : [nbL:8][ks2:4][lane:32][16B] (W1 chunk, B-frag pairs)
// WB   : [nb:16][ks2L:2][lane:32][16B] (W2 chunk)
static constexpr int SM_X  = 0;        // 32768
static constexpr int SM_H  = 32768;    // 16384
static constexpr int SM_WA = 49152;    // 16384
static constexpr int SM_WB = 65536;    // 16384
static constexpr int SM_B1 = 81920;    // 512 f32
static constexpr int SM_B2 = 83968;    // 128 f32
static constexpr int SMEM_TOTAL = 84480;

// ---------------------------------------------------------------- helpers ---
__device__ __forceinline__ uint32_t smem_u32(const void* p) {
    uint32_t a;
    asm("{ .reg .u64 t; cvta.to.shared.u64 t, %1; cvt.u32.u64 %0, t; }" : "=r"(a) : "l"(p));
    return a;
}
// pack (lo, hi) floats -> f16x2 (lo in low half)
__device__ __forceinline__ uint32_t f2h2(float lo, float hi) {
    uint32_t r;
    asm("cvt.rn.f16x2.f32 %0, %1, %2;" : "=r"(r) : "f"(hi), "f"(lo));
    return r;
}
__device__ __forceinline__ void cp16(uint32_t s, const void* g) {
    asm volatile("cp.async.ca.shared.global [%0], [%1], 16;" :: "r"(s), "l"(g));
}
#define CP_COMMIT() asm volatile("cp.async.commit_group;" ::: "memory")
#define CP_WAIT1()  asm volatile("cp.async.wait_group 1;" ::: "memory")

#define LDS128(r, addr) \
    asm volatile("ld.shared.v4.b32 {%0,%1,%2,%3}, [%4];" \
        : "=r"((r)[0]), "=r"((r)[1]), "=r"((r)[2]), "=r"((r)[3]) : "r"(addr))
#define STS64(addr, r0, r1) \
    asm volatile("st.shared.v2.b32 [%0], {%1,%2};" :: "r"(addr), "r"(r0), "r"(r1) : "memory")

__device__ __forceinline__ void mma16816(float* d, const uint32_t* a, const uint32_t* b) {
    asm volatile(
        "mma.sync.aligned.m16n8k16.row.col.f32.f16.f16.f32 "
        "{%0,%1,%2,%3}, {%4,%5,%6,%7}, {%8,%9}, {%0,%1,%2,%3};"
        : "+f"(d[0]), "+f"(d[1]), "+f"(d[2]), "+f"(d[3])
        : "r"(a[0]), "r"(a[1]), "r"(a[2]), "r"(a[3]), "r"(b[0]), "r"(b[1]));
}

// ------------------------------ weight -> fp16 B-fragment-major rearrange ---
// B-frag m16n8k16 (thread g=lane/4,t=lane%4): b0,b1=(k=2t,2t+1, col g); b2,b3=(k=2t+8,2t+9, col g)
// Storage: per (nb, ks2): [lane:32][16B] = {8B frag of ks even, 8B frag of ks odd}
__global__ void frag_kernel(const float* __restrict__ w1, const float* __restrict__ w2) {
    int i = blockIdx.x * blockDim.x + threadIdx.x;   // 0 .. 2^20-1
    int head = i >> 16, rem = i & 65535;
    {   // W1 src [head][d:128][f:512]
        int d = rem >> 9, f = rem & 511;
        int nb = f >> 3, gg = f & 7;
        int ks = d >> 4, kk = d & 15;
        int tt = (kk & 7) >> 1, lo = kk & 1, hk = (kk >> 3) & 1;
        int idx = ((((head * 64 + nb) * 4 + (ks >> 1)) * 32 + gg * 4 + tt) * 8)
                  + (ks & 1) * 4 + lo + 2 * hk;
        g_W1f[idx] = __float2half_rn(w1[i]);
    }
    {   // W2 src [head][f:512][d:128]
        int f = rem >> 7, d = rem & 127;
        int nb = d >> 3, gg = d & 7;
        int ks = f >> 4, kk = f & 15;
        int tt = (kk & 7) >> 1, lo = kk & 1, hk = (kk >> 3) & 1;
        int idx = ((((head * 16 + nb) * 16 + (ks >> 1)) * 32 + gg * 4 + tt) * 8)
                  + (ks & 1) * 4 + lo + 2 * hk;
        g_W2f[idx] = __float2half_rn(w2[i]);
    }
}

// ----------------------------------------------------------- main kernel ----
__global__ void __launch_bounds__(THREADS, 2)
ffn_kernel(const float* __restrict__ x, const float* __restrict__ b1,
           const float* __restrict__ b2, float* __restrict__ out) {
    extern __shared__ char smem[];
    const int tid  = threadIdx.x;
    const int lane = tid & 31;
    const int warp = tid >> 5;
    const int g    = lane >> 2;
    const int t    = lane & 3;
    const int wr   = warp >> 1;        // 0..3  (32-row group)
    const int wc   = warp & 1;         // 0..1

    const int head = blockIdx.y;
    const int t0   = blockIdx.x * TILE_M;
    const uint32_t sb = smem_u32(smem);

    float* b1s = reinterpret_cast<float*>(smem + SM_B1);
    float* b2s = reinterpret_cast<float*>(smem + SM_B2);

    const char* W1fb = (const char*)(g_W1f + (size_t)head * 65536);  // 128 KB/head
    const char* W2fb = (const char*)(g_W2f + (size_t)head * 65536);

    // ---- issue W1_0 (group 0) and W2_0 (group 1): 16 KB each ----
    #pragma unroll
    for (int i = 0; i < 4; ++i) {
        int s = tid + i * THREADS;                       // 1024 x 16B
        cp16(sb + SM_WA + s * 16, W1fb + s * 16);        // chunk 0 contiguous
    }
    CP_COMMIT();
    #pragma unroll
    for (int i = 0; i < 4; ++i) {
        int s = tid + i * THREADS;
        int nb = s >> 6, r = s & 63;                     // 1 KB per nb block
        cp16(sb + SM_WB + s * 16, W2fb + nb * 8192 + r * 16);
    }
    CP_COMMIT();

    // ---- biases ----
    for (int i = tid; i < FF_DIM; i += THREADS)  b1s[i] = b1[head * FF_DIM + i];
    if (tid < HEAD_DIM) b2s[tid] = b2[head * HEAD_DIM + tid];

    // ---- X tile: fp32 gmem -> fp16 A-fragment-major SMEM ----
    #pragma unroll
    for (int i = 0; i < 16; ++i) {
        int u = tid + i * THREADS;            // 4096 float4 segs
        int row = u >> 5, c4 = (u & 31) << 2;
        float4 v = *reinterpret_cast<const float4*>(
            x + (size_t)(t0 + row) * D_MODEL + head * HEAD_DIM + c4);
        int rb = row >> 4, gg = row & 7, hm = (row >> 3) & 1;
        int ks = c4 >> 4, hk = (c4 >> 3) & 1, tA = (c4 & 7) >> 1;   // tA in {0,2}
        uint32_t base = (uint32_t)(SM_X + ((rb * 8 + ks) * 32) * 16);
        int ao = (hm * 2 + hk * 4) * 2;                              // byte offset
        int ch0 = (gg * 4 + tA) ^ ks, ch1 = (gg * 4 + tA + 1) ^ ks;
        *reinterpret_cast<uint32_t*>(smem + base + ch0 * 16 + ao) = f2h2(v.x, v.y);
        *reinterpret_cast<uint32_t*>(smem + base + ch1 * 16 + ao) = f2h2(v.z, v.w);
    }
    __syncthreads();

    float acc2[2][8][4];
    #pragma unroll
    for (int mi = 0; mi < 2; ++mi)
        #pragma unroll
        for (int ni = 0; ni < 8; ++ni)
            #pragma unroll
            for (int e = 0; e < 4; ++e) acc2[mi][ni][e] = 0.0f;

    for (int c = 0; c < NCH; ++c) {
        CP_WAIT1();          // W1_c landed in WA
        __syncthreads();

        // ---- MMA1 (X[128x128] @ W1c[128x64]) in 2 ni-halves + fused relu->H ----
        #pragma unroll
        for (int nh = 0; nh < 2; ++nh) {
            float acc1[2][2][4];
            #pragma unroll
            for (int mi = 0; mi < 2; ++mi)
                #pragma unroll
                for (int n2 = 0; n2 < 2; ++n2)
                    #pragma unroll
                    for (int e = 0; e < 4; ++e) acc1[mi][n2][e] = 0.0f;

            #pragma unroll
            for (int ks2 = 0; ks2 < 4; ++ks2) {
                uint32_t a[2][2][4];
                #pragma unroll
                for (int mi = 0; mi < 2; ++mi)
                    #pragma unroll
                    for (int kp = 0; kp < 2; ++kp) {
                        int rb = wr * 2 + mi, ks = ks2 * 2 + kp;
                        LDS128(a[mi][kp],
                               sb + SM_X + (uint32_t)(((rb * 8 + ks) * 32 + (lane ^ ks)) * 16));
                    }
                #pragma unroll
                for (int n2 = 0; n2 < 2; ++n2) {
                    int nbL = wc * 4 + nh * 2 + n2;
                    uint32_t bf[4];
                    LDS128(bf, sb + SM_WA + (uint32_t)(((nbL * 4 + ks2) * 32 + lane) * 16));
                    #pragma unroll
                    for (int mi = 0; mi < 2; ++mi) {
                        mma16816(acc1[mi][n2], a[mi][0], bf);
                        mma16816(acc1[mi][n2], a[mi][1], bf + 2);
                    }
                }
            }
            // bias + relu + fp16 -> Hfrag (A-frag layout for MMA2)
            const int ksH = wc * 2 + nh;
            #pragma unroll
            for (int mi = 0; mi < 2; ++mi)
                #pragma unroll
                for (int n2 = 0; n2 < 2; ++n2) {
                    int ni  = nh * 2 + n2;
                    int colb = c * FFC + wc * 32 + ni * 8 + 2 * t;
                    float v0 = fmaxf(acc1[mi][n2][0] + b1s[colb],     0.0f);
                    float v1 = fmaxf(acc1[mi][n2][1] + b1s[colb + 1], 0.0f);
                    float v2 = fmaxf(acc1[mi][n2][2] + b1s[colb],     0.0f);
                    float v3 = fmaxf(acc1[mi][n2][3] + b1s[colb + 1], 0.0f);
                    int rb = wr * 2 + mi;
                    uint32_t addr = sb + SM_H +
                        (uint32_t)((((rb * 4 + ksH) * 32) + (g * 4 + (t ^ ksH))) * 16 + n2 * 8);
                    STS64(addr, f2h2(v0, v1), f2h2(v2, v3));
                }
        }
        __syncthreads();     // WA free + Hfrag published (after next barrier)

        // ---- prefetch W1_{c+1} ----
        if (c + 1 < NCH) {
            #pragma unroll
            for (int i = 0; i < 4; ++i) {
                int s = tid + i * THREADS;
                cp16(sb + SM_WA + s * 16, W1fb + (c + 1) * 16384 + s * 16);
            }
        }
        CP_COMMIT();

        CP_WAIT1();          // W2_c landed in WB
        __syncthreads();     // Hfrag visible to all warps

        // ---- MMA2: out[128x128] += H[128x64] @ W2c[64x128] ----
        #pragma unroll
        for (int ks2 = 0; ks2 < 2; ++ks2) {
            uint32_t a[2][2][4];
            #pragma unroll
            for (int mi = 0; mi < 2; ++mi)
                #pragma unroll
                for (int kp = 0; kp < 2; ++kp) {
                    int rb = wr * 2 + mi, ksH = ks2 * 2 + kp;
                    LDS128(a[mi][kp],
                           sb + SM_H + (uint32_t)(((rb * 4 + ksH) * 32 + (lane ^ ksH)) * 16));
                }
            #pragma unroll
            for (int ni = 0; ni < 8; ++ni) {
                int nb = wc * 8 + ni;
                uint32_t bf[4];
                LDS128(bf, sb + SM_WB + (uint32_t)(((nb * 2 + ks2) * 32 + lane) * 16));
                #pragma unroll
                for (int mi = 0; mi < 2; ++mi) {
                    mma16816(acc2[mi][ni], a[mi][0], bf);
                    mma16816(acc2[mi][ni], a[mi][1], bf + 2);
                }
            }
        }
        __syncthreads();     // WB free, H reads done

        // ---- prefetch W2_{c+1} ----
        if (c + 1 < NCH) {
            #pragma unroll
            for (int i = 0; i < 4; ++i) {
                int s = tid + i * THREADS;
                int nb = s >> 6, r = s & 63;
                cp16(sb + SM_WB + s * 16, W2fb + nb * 8192 + (c + 1) * 1024 + r * 16);
            }
        }
        CP_COMMIT();
    }

    // ---- epilogue: acc2 + b2 -> gmem (float2 stores, 32B sectors fully used) ----
    #pragma unroll
    for (int mi = 0; mi < 2; ++mi)
        #pragma unroll
        for (int ni = 0; ni < 8; ++ni) {
            int r1 = t0 + wr * 32 + mi * 16 + g;
            int cg = wc * 64 + ni * 8 + 2 * t;
            float2 v01, v23;
            v01.x = acc2[mi][ni][0] + b2s[cg];
            v01.y = acc2[mi][ni][1] + b2s[cg + 1];
            v23.x = acc2[mi][ni][2] + b2s[cg];
            v23.y = acc2[mi][ni][3] + b2s[cg + 1];
            *reinterpret_cast<float2*>(out + (size_t)r1 * D_MODEL + head * HEAD_DIM + cg) = v01;
            *reinterpret_cast<float2*>(out + (size_t)(r1 + 8) * D_MODEL + head * HEAD_DIM + cg) = v23;
        }
}

// -------------------------------------------------------------- launch ------
extern "C" void kernel_launch(void* const* d_in, const int* in_sizes, int n_in,
                              void* d_out, int out_size) {
    const float* x  = (const float*)d_in[0];
    const float* W1 = (const float*)d_in[1];
    const float* b1 = (const float*)d_in[2];
    const float* W2 = (const float*)d_in[3];
    const float* b2 = (const float*)d_in[4];
    float* out = (float*)d_out;

    frag_kernel<<<4096, 256>>>(W1, W2);   // 2^20 threads, exact cover

    cudaFuncSetAttribute(ffn_kernel, cudaFuncAttributeMaxDynamicSharedMemorySize, SMEM_TOTAL);
    ffn_kernel<<<dim3(16384 / TILE_M, N_HEADS), THREADS, SMEM_TOTAL>>>(x, b1, b2, out);
}

// round 5
// speedup vs baseline: 1.8299x; 1.1045x over previous
#include <cuda_runtime.h>
#include <cuda_fp16.h>
#include <cstdint>

#define N_HEADS   16
#define HEAD_DIM  128
#define FF_DIM    512
#define D_MODEL   2048
#define TILE_M    128
#define FFC       64
#define NCH       (FF_DIM / FFC)   // 8
#define THREADS   256

// fp16 weights in B-fragment-major order (built once per launch)
__device__ __half g_W1f[N_HEADS * HEAD_DIM * FF_DIM];   // 2 MB
__device__ __half g_W2f[N_HEADS * FF_DIM * HEAD_DIM];   // 2 MB

// --------------------------------------------------------- SMEM layout ------
// Xfrag: [rb:8][ks:8][chunk:32][16B]   A-frags, chunk index = (g*4+t)^ks
// Hfrag: [rb:8][ksH:4][lane:32][16B]   ready-made MMA2 A-frags, per-lane direct
// WA   : [nbL:8][ks2:4][lane:32][16B]  W1 chunk B-frag pairs
// WB   : [nb:16][ks2:2][lane:32][16B]  W2 chunk B-frag pairs
static constexpr int SM_X  = 0;        // 32768
static constexpr int SM_H  = 32768;    // 16384
static constexpr int SM_WA = 49152;    // 16384
static constexpr int SM_WB = 65536;    // 16384
static constexpr int SM_B1 = 81920;    // 512 f32
static constexpr int SM_B2 = 83968;    // 128 f32
static constexpr int SMEM_TOTAL = 84480;

// ---------------------------------------------------------------- helpers ---
__device__ __forceinline__ uint32_t smem_u32(const void* p) {
    uint32_t a;
    asm("{ .reg .u64 t; cvta.to.shared.u64 t, %1; cvt.u32.u64 %0, t; }" : "=r"(a) : "l"(p));
    return a;
}
__device__ __forceinline__ uint32_t f2h2(float lo, float hi) {
    uint32_t r;
    asm("cvt.rn.f16x2.f32 %0, %1, %2;" : "=r"(r) : "f"(hi), "f"(lo));
    return r;
}
__device__ __forceinline__ void cp16(uint32_t s, const void* g) {
    asm volatile("cp.async.ca.shared.global [%0], [%1], 16;" :: "r"(s), "l"(g));
}
#define CP_COMMIT() asm volatile("cp.async.commit_group;" ::: "memory")
#define CP_WAIT1()  asm volatile("cp.async.wait_group 1;" ::: "memory")

#define LDS128(r, addr) \
    asm volatile("ld.shared.v4.b32 {%0,%1,%2,%3}, [%4];" \
        : "=r"((r)[0]), "=r"((r)[1]), "=r"((r)[2]), "=r"((r)[3]) : "r"(addr))
#define STS128(addr, r) \
    asm volatile("st.shared.v4.b32 [%0], {%1,%2,%3,%4};" \
        :: "r"(addr), "r"((r)[0]), "r"((r)[1]), "r"((r)[2]), "r"((r)[3]) : "memory")

__device__ __forceinline__ void mma16816(float* d, const uint32_t* a, const uint32_t* b) {
    asm volatile(
        "mma.sync.aligned.m16n8k16.row.col.f32.f16.f16.f32 "
        "{%0,%1,%2,%3}, {%4,%5,%6,%7}, {%8,%9}, {%0,%1,%2,%3};"
        : "+f"(d[0]), "+f"(d[1]), "+f"(d[2]), "+f"(d[3])
        : "r"(a[0]), "r"(a[1]), "r"(a[2]), "r"(a[3]), "r"(b[0]), "r"(b[1]));
}

// ------------------------------ weight -> fp16 B-fragment-major rearrange ---
__global__ void frag_kernel(const float* __restrict__ w1, const float* __restrict__ w2) {
    int i = blockIdx.x * blockDim.x + threadIdx.x;   // 0 .. 2^20-1
    int head = i >> 16, rem = i & 65535;
    {   // W1 src [head][d:128][f:512]
        int d = rem >> 9, f = rem & 511;
        int nb = f >> 3, gg = f & 7;
        int ks = d >> 4, kk = d & 15;
        int tt = (kk & 7) >> 1, lo = kk & 1, hk = (kk >> 3) & 1;
        int idx = ((((head * 64 + nb) * 4 + (ks >> 1)) * 32 + gg * 4 + tt) * 8)
                  + (ks & 1) * 4 + lo + 2 * hk;
        g_W1f[idx] = __float2half_rn(w1[i]);
    }
    {   // W2 src [head][f:512][d:128]
        int f = rem >> 7, d = rem & 127;
        int nb = d >> 3, gg = d & 7;
        int ks = f >> 4, kk = f & 15;
        int tt = (kk & 7) >> 1, lo = kk & 1, hk = (kk >> 3) & 1;
        int idx = ((((head * 16 + nb) * 16 + (ks >> 1)) * 32 + gg * 4 + tt) * 8)
                  + (ks & 1) * 4 + lo + 2 * hk;
        g_W2f[idx] = __float2half_rn(w2[i]);
    }
}

// ----------------------------------------------------------- main kernel ----
__global__ void __launch_bounds__(THREADS, 2)
ffn_kernel(const float* __restrict__ x, const float* __restrict__ b1,
           const float* __restrict__ b2, float* __restrict__ out) {
    extern __shared__ char smem[];
    const int tid  = threadIdx.x;
    const int lane = tid & 31;
    const int warp = tid >> 5;
    const int g    = lane >> 2;
    const int t    = lane & 3;
    const int wr   = warp >> 1;        // 0..3  (32-row group)
    const int wc   = warp & 1;         // 0..1  (32-col half of chunk)

    const int head = blockIdx.y;
    const int t0   = blockIdx.x * TILE_M;
    const uint32_t sb = smem_u32(smem);

    float* b1s = reinterpret_cast<float*>(smem + SM_B1);
    float* b2s = reinterpret_cast<float*>(smem + SM_B2);

    const char* W1fb = (const char*)(g_W1f + (size_t)head * 65536);
    const char* W2fb = (const char*)(g_W2f + (size_t)head * 65536);

    // ---- issue W1_0 (group 0) and W2_0 (group 1): 16 KB each ----
    #pragma unroll
    for (int i = 0; i < 4; ++i) {
        int s = tid + i * THREADS;
        cp16(sb + SM_WA + s * 16, W1fb + s * 16);
    }
    CP_COMMIT();
    #pragma unroll
    for (int i = 0; i < 4; ++i) {
        int s = tid + i * THREADS;
        int nb = s >> 6, r = s & 63;
        cp16(sb + SM_WB + s * 16, W2fb + nb * 8192 + r * 16);
    }
    CP_COMMIT();

    // ---- biases ----
    for (int i = tid; i < FF_DIM; i += THREADS)  b1s[i] = b1[head * FF_DIM + i];
    if (tid < HEAD_DIM) b2s[tid] = b2[head * HEAD_DIM + tid];

    // ---- X tile: fp32 gmem -> fp16 A-fragment-major SMEM (XOR swizzled) ----
    #pragma unroll
    for (int i = 0; i < 16; ++i) {
        int u = tid + i * THREADS;            // 4096 float4 segs
        int row = u >> 5, c4 = (u & 31) << 2;
        float4 v = *reinterpret_cast<const float4*>(
            x + (size_t)(t0 + row) * D_MODEL + head * HEAD_DIM + c4);
        int rb = row >> 4, gg = row & 7, hm = (row >> 3) & 1;
        int ks = c4 >> 4, hk = (c4 >> 3) & 1, tA = (c4 & 7) >> 1;
        uint32_t base = (uint32_t)(SM_X + ((rb * 8 + ks) * 32) * 16);
        int ao = (hm * 2 + hk * 4) * 2;
        int ch0 = (gg * 4 + tA) ^ ks, ch1 = (gg * 4 + tA + 1) ^ ks;
        *reinterpret_cast<uint32_t*>(smem + base + ch0 * 16 + ao) = f2h2(v.x, v.y);
        *reinterpret_cast<uint32_t*>(smem + base + ch1 * 16 + ao) = f2h2(v.z, v.w);
    }
    __syncthreads();

    float acc2[2][8][4];
    #pragma unroll
    for (int mi = 0; mi < 2; ++mi)
        #pragma unroll
        for (int ni = 0; ni < 8; ++ni)
            #pragma unroll
            for (int e = 0; e < 4; ++e) acc2[mi][ni][e] = 0.0f;

    for (int c = 0; c < NCH; ++c) {
        CP_WAIT1();          // W1_c landed in WA
        __syncthreads();     // also: H_{c-1} cross-reads & WB_{c-1} reads done

        // ---- MMA1: hchunk[128x64] = X[128x128] @ W1c[128x64], A hoisted ----
        float acc1[2][4][4];
        #pragma unroll
        for (int mi = 0; mi < 2; ++mi)
            #pragma unroll
            for (int ni = 0; ni < 4; ++ni)
                #pragma unroll
                for (int e = 0; e < 4; ++e) acc1[mi][ni][e] = 0.0f;

        #pragma unroll
        for (int ks2 = 0; ks2 < 4; ++ks2) {
            uint32_t a[2][2][4];
            #pragma unroll
            for (int mi = 0; mi < 2; ++mi)
                #pragma unroll
                for (int kp = 0; kp < 2; ++kp) {
                    int rb = wr * 2 + mi, ks = ks2 * 2 + kp;
                    LDS128(a[mi][kp],
                           sb + SM_X + (uint32_t)(((rb * 8 + ks) * 32 + (lane ^ ks)) * 16));
                }
            #pragma unroll
            for (int nb = 0; nb < 4; ++nb) {
                int nbL = wc * 4 + nb;
                uint32_t bf[4];
                LDS128(bf, sb + SM_WA + (uint32_t)(((nbL * 4 + ks2) * 32 + lane) * 16));
                #pragma unroll
                for (int mi = 0; mi < 2; ++mi) {
                    mma16816(acc1[mi][nb], a[mi][0], bf);
                    mma16816(acc1[mi][nb], a[mi][1], bf + 2);
                }
            }
        }

        // ---- bias + relu -> own MMA2 A-frags (regs) + publish to H ----
        uint32_t aH[2][2][4];
        #pragma unroll
        for (int mi = 0; mi < 2; ++mi)
            #pragma unroll
            for (int ni = 0; ni < 4; ++ni) {
                int colb = c * FFC + wc * 32 + ni * 8 + 2 * t;
                float v0 = fmaxf(acc1[mi][ni][0] + b1s[colb],     0.0f);
                float v1 = fmaxf(acc1[mi][ni][1] + b1s[colb + 1], 0.0f);
                float v2 = fmaxf(acc1[mi][ni][2] + b1s[colb],     0.0f);
                float v3 = fmaxf(acc1[mi][ni][3] + b1s[colb + 1], 0.0f);
                int ksl = ni >> 1, off = (ni & 1) * 2;
                aH[mi][ksl][off]     = f2h2(v0, v1);   // row g   half
                aH[mi][ksl][off + 1] = f2h2(v2, v3);   // row g+8 half
            }
        #pragma unroll
        for (int mi = 0; mi < 2; ++mi)
            #pragma unroll
            for (int ksl = 0; ksl < 2; ++ksl) {
                int rb = wr * 2 + mi, ksH = wc * 2 + ksl;
                STS128(sb + SM_H + (uint32_t)(((rb * 4 + ksH) * 32 + lane) * 16),
                       aH[mi][ksl]);
            }
        __syncthreads();     // H published; WA reads done by all warps

        // ---- prefetch W1_{c+1} into WA ----
        if (c + 1 < NCH) {
            #pragma unroll
            for (int i = 0; i < 4; ++i) {
                int s = tid + i * THREADS;
                cp16(sb + SM_WA + s * 16, W1fb + (c + 1) * 16384 + s * 16);
            }
        }
        CP_COMMIT();

        CP_WAIT1();          // W2_c landed in WB
        __syncthreads();

        // ---- cross half of H (partner warp's k-range) ----
        uint32_t ax[2][2][4];
        #pragma unroll
        for (int mi = 0; mi < 2; ++mi)
            #pragma unroll
            for (int ksl = 0; ksl < 2; ++ksl) {
                int rb = wr * 2 + mi, ksH = (1 - wc) * 2 + ksl;
                LDS128(ax[mi][ksl],
                       sb + SM_H + (uint32_t)(((rb * 4 + ksH) * 32 + lane) * 16));
            }

        // ---- MMA2: out[128x128] += H[128x64] @ W2c[64x128], own half first ----
        #pragma unroll
        for (int ph = 0; ph < 2; ++ph) {
            const int ks2 = (ph == 0) ? wc : (1 - wc);   // uniform per warp
            #pragma unroll
            for (int ni = 0; ni < 8; ++ni) {
                int nb = wc * 8 + ni;
                uint32_t bf[4];
                LDS128(bf, sb + SM_WB + (uint32_t)(((nb * 2 + ks2) * 32 + lane) * 16));
                if (ph == 0) {
                    #pragma unroll
                    for (int mi = 0; mi < 2; ++mi) {
                        mma16816(acc2[mi][ni], aH[mi][0], bf);
                        mma16816(acc2[mi][ni], aH[mi][1], bf + 2);
                    }
                } else {
                    #pragma unroll
                    for (int mi = 0; mi < 2; ++mi) {
                        mma16816(acc2[mi][ni], ax[mi][0], bf);
                        mma16816(acc2[mi][ni], ax[mi][1], bf + 2);
                    }
                }
            }
        }
        __syncthreads();     // WB free, H cross-reads done

        // ---- prefetch W2_{c+1} into WB ----
        if (c + 1 < NCH) {
            #pragma unroll
            for (int i = 0; i < 4; ++i) {
                int s = tid + i * THREADS;
                int nb = s >> 6, r = s & 63;
                cp16(sb + SM_WB + s * 16, W2fb + nb * 8192 + (c + 1) * 1024 + r * 16);
            }
        }
        CP_COMMIT();
    }

    // ---- epilogue: acc2 + b2 -> gmem ----
    #pragma unroll
    for (int mi = 0; mi < 2; ++mi)
        #pragma unroll
        for (int ni = 0; ni < 8; ++ni) {
            int r1 = t0 + wr * 32 + mi * 16 + g;
            int cg = wc * 64 + ni * 8 + 2 * t;
            float2 v01, v23;
            v01.x = acc2[mi][ni][0] + b2s[cg];
            v01.y = acc2[mi][ni][1] + b2s[cg + 1];
            v23.x = acc2[mi][ni][2] + b2s[cg];
            v23.y = acc2[mi][ni][3] + b2s[cg + 1];
            *reinterpret_cast<float2*>(out + (size_t)r1 * D_MODEL + head * HEAD_DIM + cg) = v01;
            *reinterpret_cast<float2*>(out + (size_t)(r1 + 8) * D_MODEL + head * HEAD_DIM + cg) = v23;
        }
}

// -------------------------------------------------------------- launch ------
extern "C" void kernel_launch(void* const* d_in, const int* in_sizes, int n_in,
                              void* d_out, int out_size) {
    const float* x  = (const float*)d_in[0];
    const float* W1 = (const float*)d_in[1];
    const float* b1 = (const float*)d_in[2];
    const float* W2 = (const float*)d_in[3];
    const float* b2 = (const float*)d_in[4];
    float* out = (float*)d_out;

    frag_kernel<<<4096, 256>>>(W1, W2);

    cudaFuncSetAttribute(ffn_kernel, cudaFuncAttributeMaxDynamicSharedMemorySize, SMEM_TOTAL);
    ffn_kernel<<<dim3(16384 / TILE_M, N_HEADS), THREADS, SMEM_TOTAL>>>(x, b1, b2, out);
}

// round 6
// speedup vs baseline: 1.8636x; 1.0184x over previous
#include <cuda_runtime.h>
#include <cuda_fp16.h>
#include <cstdint>

#define N_HEADS   16
#define HEAD_DIM  128
#define FF_DIM    512
#define D_MODEL   2048
#define TILE_M    128
#define FFC       64
#define NCH       (FF_DIM / FFC)   // 8
#define THREADS   256

// fp16 weights in B-fragment-major order (built once per launch)
__device__ __half g_W1f[N_HEADS * HEAD_DIM * FF_DIM];   // 2 MB
__device__ __half g_W2f[N_HEADS * FF_DIM * HEAD_DIM];   // 2 MB

// --------------------------------------------------------- SMEM layout ------
// H   : [rb:8][ksH:4][lane:32][16B]    ready-made MMA2 A-frags
// WA0/1: [nbL:8][ks2:4][lane:32][16B]  W1 chunk B-frag pairs (double buffer)
// WB0/1: [nb:16][ks2:2][lane:32][16B]  W2 chunk B-frag pairs (double buffer)
// X staging (prologue only) aliases WB0..WB1 (32 KB)
static constexpr int SM_H   = 0;        // 16384
static constexpr int SM_WA0 = 16384;    // 16384
static constexpr int SM_WA1 = 32768;    // 16384
static constexpr int SM_WB0 = 49152;    // 16384
static constexpr int SM_WB1 = 65536;    // 16384
static constexpr int SM_XST = 49152;    // staging alias (32 KB over WB0+WB1)
static constexpr int SM_B1  = 81920;    // 512 f32
static constexpr int SM_B2  = 83968;    // 128 f32
static constexpr int SMEM_TOTAL = 84480;

// ---------------------------------------------------------------- helpers ---
__device__ __forceinline__ uint32_t smem_u32(const void* p) {
    uint32_t a;
    asm("{ .reg .u64 t; cvta.to.shared.u64 t, %1; cvt.u32.u64 %0, t; }" : "=r"(a) : "l"(p));
    return a;
}
__device__ __forceinline__ uint32_t f2h2(float lo, float hi) {
    uint32_t r;
    asm("cvt.rn.f16x2.f32 %0, %1, %2;" : "=r"(r) : "f"(hi), "f"(lo));
    return r;
}
__device__ __forceinline__ void cp16(uint32_t s, const void* g) {
    asm volatile("cp.async.ca.shared.global [%0], [%1], 16;" :: "r"(s), "l"(g));
}
#define CP_COMMIT() asm volatile("cp.async.commit_group;" ::: "memory")
#define CP_WAIT1()  asm volatile("cp.async.wait_group 1;" ::: "memory")

#define LDS128(r, addr) \
    asm volatile("ld.shared.v4.b32 {%0,%1,%2,%3}, [%4];" \
        : "=r"((r)[0]), "=r"((r)[1]), "=r"((r)[2]), "=r"((r)[3]) : "r"(addr))
#define STS128(addr, r) \
    asm volatile("st.shared.v4.b32 [%0], {%1,%2,%3,%4};" \
        :: "r"(addr), "r"((r)[0]), "r"((r)[1]), "r"((r)[2]), "r"((r)[3]) : "memory")

__device__ __forceinline__ void mma16816(float* d, const uint32_t* a, const uint32_t* b) {
    asm volatile(
        "mma.sync.aligned.m16n8k16.row.col.f32.f16.f16.f32 "
        "{%0,%1,%2,%3}, {%4,%5,%6,%7}, {%8,%9}, {%0,%1,%2,%3};"
        : "+f"(d[0]), "+f"(d[1]), "+f"(d[2]), "+f"(d[3])
        : "r"(a[0]), "r"(a[1]), "r"(a[2]), "r"(a[3]), "r"(b[0]), "r"(b[1]));
}

// ------------------------------ weight -> fp16 B-fragment-major rearrange ---
__global__ void frag_kernel(const float* __restrict__ w1, const float* __restrict__ w2) {
    int i = blockIdx.x * blockDim.x + threadIdx.x;   // 0 .. 2^20-1
    int head = i >> 16, rem = i & 65535;
    {   // W1 src [head][d:128][f:512]
        int d = rem >> 9, f = rem & 511;
        int nb = f >> 3, gg = f & 7;
        int ks = d >> 4, kk = d & 15;
        int tt = (kk & 7) >> 1, lo = kk & 1, hk = (kk >> 3) & 1;
        int idx = ((((head * 64 + nb) * 4 + (ks >> 1)) * 32 + gg * 4 + tt) * 8)
                  + (ks & 1) * 4 + lo + 2 * hk;
        g_W1f[idx] = __float2half_rn(w1[i]);
    }
    {   // W2 src [head][f:512][d:128]
        int f = rem >> 7, d = rem & 127;
        int nb = d >> 3, gg = d & 7;
        int ks = f >> 4, kk = f & 15;
        int tt = (kk & 7) >> 1, lo = kk & 1, hk = (kk >> 3) & 1;
        int idx = ((((head * 16 + nb) * 16 + (ks >> 1)) * 32 + gg * 4 + tt) * 8)
                  + (ks & 1) * 4 + lo + 2 * hk;
        g_W2f[idx] = __float2half_rn(w2[i]);
    }
}

// ----------------------------------------------------------- main kernel ----
__global__ void __launch_bounds__(THREADS, 1)
ffn_kernel(const float* __restrict__ x, const float* __restrict__ b1,
           const float* __restrict__ b2, float* __restrict__ out) {
    extern __shared__ char smem[];
    const int tid  = threadIdx.x;
    const int lane = tid & 31;
    const int warp = tid >> 5;
    const int g    = lane >> 2;
    const int t    = lane & 3;
    const int wr   = warp >> 1;        // 0..3  (32-row group)
    const int wc   = warp & 1;         // 0..1  (32-col half of chunk)

    const int head = blockIdx.y;
    const int t0   = blockIdx.x * TILE_M;
    const uint32_t sb = smem_u32(smem);

    float* b1s = reinterpret_cast<float*>(smem + SM_B1);
    float* b2s = reinterpret_cast<float*>(smem + SM_B2);

    const char* W1fb = (const char*)(g_W1f + (size_t)head * 65536);
    const char* W2fb = (const char*)(g_W2f + (size_t)head * 65536);

    // ---- G0: W1_0 -> WA0 and W1_1 -> WA1 (one group) ----
    #pragma unroll
    for (int i = 0; i < 4; ++i) {
        int s = tid + i * THREADS;
        cp16(sb + SM_WA0 + s * 16, W1fb + s * 16);
        cp16(sb + SM_WA1 + s * 16, W1fb + 16384 + s * 16);
    }
    CP_COMMIT();

    // ---- biases ----
    for (int i = tid; i < FF_DIM; i += THREADS)  b1s[i] = b1[head * FF_DIM + i];
    if (tid < HEAD_DIM) b2s[tid] = b2[head * HEAD_DIM + tid];

    // ---- X tile: fp32 gmem -> fp16 A-fragment-major staging (aliases WB) ----
    #pragma unroll
    for (int i = 0; i < 16; ++i) {
        int u = tid + i * THREADS;            // 4096 float4 segs
        int row = u >> 5, c4 = (u & 31) << 2;
        float4 v = *reinterpret_cast<const float4*>(
            x + (size_t)(t0 + row) * D_MODEL + head * HEAD_DIM + c4);
        int rb = row >> 4, gg = row & 7, hm = (row >> 3) & 1;
        int ks = c4 >> 4, hk = (c4 >> 3) & 1, tA = (c4 & 7) >> 1;
        uint32_t base = (uint32_t)(SM_XST + ((rb * 8 + ks) * 32) * 16);
        int ao = (hm * 2 + hk * 4) * 2;
        int ch0 = (gg * 4 + tA) ^ ks, ch1 = (gg * 4 + tA + 1) ^ ks;
        *reinterpret_cast<uint32_t*>(smem + base + ch0 * 16 + ao) = f2h2(v.x, v.y);
        *reinterpret_cast<uint32_t*>(smem + base + ch1 * 16 + ao) = f2h2(v.z, v.w);
    }
    __syncthreads();

    // ---- extract X A-fragments into registers (once) ----
    uint32_t xf[2][8][4];
    #pragma unroll
    for (int mi = 0; mi < 2; ++mi)
        #pragma unroll
        for (int ks = 0; ks < 8; ++ks) {
            int rb = wr * 2 + mi;
            LDS128(xf[mi][ks],
                   sb + SM_XST + (uint32_t)(((rb * 8 + ks) * 32 + (lane ^ ks)) * 16));
        }
    __syncthreads();   // staging reads done; WB region reusable

    // ---- G1: W2_0 -> WB0 ; G2: W2_1 -> WB1 ----
    #pragma unroll
    for (int i = 0; i < 4; ++i) {
        int s = tid + i * THREADS;
        int nb = s >> 6, r = s & 63;
        cp16(sb + SM_WB0 + s * 16, W2fb + nb * 8192 + r * 16);
    }
    CP_COMMIT();
    #pragma unroll
    for (int i = 0; i < 4; ++i) {
        int s = tid + i * THREADS;
        int nb = s >> 6, r = s & 63;
        cp16(sb + SM_WB1 + s * 16, W2fb + nb * 8192 + 1024 + r * 16);
    }
    CP_COMMIT();

    float acc2[2][8][4];
    #pragma unroll
    for (int mi = 0; mi < 2; ++mi)
        #pragma unroll
        for (int ni = 0; ni < 8; ++ni)
            #pragma unroll
            for (int e = 0; e < 4; ++e) acc2[mi][ni][e] = 0.0f;

    for (int c = 0; c < NCH; ++c) {
        const uint32_t wa = sb + ((c & 1) ? SM_WA1 : SM_WA0);
        const uint32_t wb = sb + ((c & 1) ? SM_WB1 : SM_WB0);

        CP_WAIT1();          // pair(c) fully arrived (pair(c+1) may pend)
        __syncthreads();     // arrival visible; H_{c-1} cross-reads done

        // ---- MMA1: A from registers, B from WA[c&1] ----
        float acc1[2][4][4];
        #pragma unroll
        for (int mi = 0; mi < 2; ++mi)
            #pragma unroll
            for (int ni = 0; ni < 4; ++ni)
                #pragma unroll
                for (int e = 0; e < 4; ++e) acc1[mi][ni][e] = 0.0f;

        #pragma unroll
        for (int ks2 = 0; ks2 < 4; ++ks2) {
            #pragma unroll
            for (int nb = 0; nb < 4; ++nb) {
                int nbL = wc * 4 + nb;
                uint32_t bf[4];
                LDS128(bf, wa + (uint32_t)(((nbL * 4 + ks2) * 32 + lane) * 16));
                #pragma unroll
                for (int mi = 0; mi < 2; ++mi) {
                    mma16816(acc1[mi][nb], xf[mi][ks2 * 2],     bf);
                    mma16816(acc1[mi][nb], xf[mi][ks2 * 2 + 1], bf + 2);
                }
            }
        }

        // ---- bias + relu -> own MMA2 A-frags (regs) + publish to H ----
        uint32_t aH[2][2][4];
        #pragma unroll
        for (int mi = 0; mi < 2; ++mi)
            #pragma unroll
            for (int ni = 0; ni < 4; ++ni) {
                int colb = c * FFC + wc * 32 + ni * 8 + 2 * t;
                float v0 = fmaxf(acc1[mi][ni][0] + b1s[colb],     0.0f);
                float v1 = fmaxf(acc1[mi][ni][1] + b1s[colb + 1], 0.0f);
                float v2 = fmaxf(acc1[mi][ni][2] + b1s[colb],     0.0f);
                float v3 = fmaxf(acc1[mi][ni][3] + b1s[colb + 1], 0.0f);
                int ksl = ni >> 1, off = (ni & 1) * 2;
                aH[mi][ksl][off]     = f2h2(v0, v1);
                aH[mi][ksl][off + 1] = f2h2(v2, v3);
            }
        #pragma unroll
        for (int mi = 0; mi < 2; ++mi)
            #pragma unroll
            for (int ksl = 0; ksl < 2; ++ksl) {
                int rb = wr * 2 + mi, ksH = wc * 2 + ksl;
                STS128(sb + SM_H + (uint32_t)(((rb * 4 + ksH) * 32 + lane) * 16),
                       aH[mi][ksl]);
            }
        __syncthreads();     // H published

        // ---- cross half of H (partner warp's k-range) ----
        uint32_t ax[2][2][4];
        #pragma unroll
        for (int mi = 0; mi < 2; ++mi)
            #pragma unroll
            for (int ksl = 0; ksl < 2; ++ksl) {
                int rb = wr * 2 + mi, ksH = (1 - wc) * 2 + ksl;
                LDS128(ax[mi][ksl],
                       sb + SM_H + (uint32_t)(((rb * 4 + ksH) * 32 + lane) * 16));
            }

        // ---- MMA2: own half first, then cross half; B from WB[c&1] ----
        #pragma unroll
        for (int ph = 0; ph < 2; ++ph) {
            const int ks2 = (ph == 0) ? wc : (1 - wc);   // uniform per warp
            #pragma unroll
            for (int ni = 0; ni < 8; ++ni) {
                int nb = wc * 8 + ni;
                uint32_t bf[4];
                LDS128(bf, wb + (uint32_t)(((nb * 2 + ks2) * 32 + lane) * 16));
                if (ph == 0) {
                    #pragma unroll
                    for (int mi = 0; mi < 2; ++mi) {
                        mma16816(acc2[mi][ni], aH[mi][0], bf);
                        mma16816(acc2[mi][ni], aH[mi][1], bf + 2);
                    }
                } else {
                    #pragma unroll
                    for (int mi = 0; mi < 2; ++mi) {
                        mma16816(acc2[mi][ni], ax[mi][0], bf);
                        mma16816(acc2[mi][ni], ax[mi][1], bf + 2);
                    }
                }
            }
        }
        __syncthreads();     // all reads of WA/WB[c&1] and H done

        // ---- issue pair(c+2) into the buffers just freed (one group) ----
        if (c + 2 < NCH) {
            #pragma unroll
            for (int i = 0; i < 4; ++i) {
                int s = tid + i * THREADS;
                cp16(wa + s * 16, W1fb + (c + 2) * 16384 + s * 16);
            }
            #pragma unroll
            for (int i = 0; i < 4; ++i) {
                int s = tid + i * THREADS;
                int nb = s >> 6, r = s & 63;
                cp16(wb + s * 16, W2fb + nb * 8192 + (c + 2) * 1024 + r * 16);
            }
        }
        CP_COMMIT();         // empty group when c+2 >= NCH keeps counts aligned
    }

    // ---- epilogue: acc2 + b2 -> gmem ----
    #pragma unroll
    for (int mi = 0; mi < 2; ++mi)
        #pragma unroll
        for (int ni = 0; ni < 8; ++ni) {
            int r1 = t0 + wr * 32 + mi * 16 + g;
            int cg = wc * 64 + ni * 8 + 2 * t;
            float2 v01, v23;
            v01.x = acc2[mi][ni][0] + b2s[cg];
            v01.y = acc2[mi][ni][1] + b2s[cg + 1];
            v23.x = acc2[mi][ni][2] + b2s[cg];
            v23.y = acc2[mi][ni][3] + b2s[cg + 1];
            *reinterpret_cast<float2*>(out + (size_t)r1 * D_MODEL + head * HEAD_DIM + cg) = v01;
            *reinterpret_cast<float2*>(out + (size_t)(r1 + 8) * D_MODEL + head * HEAD_DIM + cg) = v23;
        }
}

// -------------------------------------------------------------- launch ------
extern "C" void kernel_launch(void* const* d_in, const int* in_sizes, int n_in,
                              void* d_out, int out_size) {
    const float* x  = (const float*)d_in[0];
    const float* W1 = (const float*)d_in[1];
    const float* b1 = (const float*)d_in[2];
    const float* W2 = (const float*)d_in[3];
    const float* b2 = (const float*)d_in[4];
    float* out = (float*)d_out;

    frag_kernel<<<4096, 256>>>(W1, W2);

    cudaFuncSetAttribute(ffn_kernel, cudaFuncAttributeMaxDynamicSharedMemorySize, SMEM_TOTAL);
    ffn_kernel<<<dim3(16384 / TILE_M, N_HEADS), THREADS, SMEM_TOTAL>>>(x, b1, b2, out);
}